// round 15
// baseline (speedup 1.0000x reference)
#include <cuda_runtime.h>
#include <cuda_bf16.h>
#include <cstdint>
#include <math.h>

// ---------------------------------------------------------------------------
// Problem constants
// ---------------------------------------------------------------------------
#define BB   16
#define CC   512
#define NTOK 1024
#define GG   8
#define CPG  64
#define EPSV 1e-5f
#define CN   (CC * NTOK)     // 524288
#define SSTR (NTOK * NTOK)   // 1048576
#define NGRP 4               // batch groups (4 pipeline phases)
#define GB   (BB / NGRP)     // 4 batches per group

typedef __nv_bfloat16 bf16;

// Scratch (device globals — no allocations allowed)
__device__ bf16  g_xn [BB * CN];          // token-major normalized input [b][n][c]
__device__ bf16  g_qk [BB * NTOK * 1024]; // packed [b][n][0:512)=Q, [512:1024)=K
__device__ bf16  g_v  [BB * CN];          // channel-major [b][c][j]
__device__ float g_s  [BB * SSTR];        // S[b][i][j] fp32 (pre-softmax)
__device__ bf16  g_p  [BB * SSTR];        // P[b][i][j] bf16 (post-softmax)
__device__ bf16  g_o  [BB * CN];          // [b][n][c]
__device__ bf16  g_w  [4 * CC * CC];      // bf16 wq, wk, wv, wp (wq||wk packed)
__device__ float g_bqk[1024];             // packed bq||bk

// ---------------------------------------------------------------------------
// Helpers
// ---------------------------------------------------------------------------
__device__ __forceinline__ uint32_t smem_u32(const void* p) {
    uint32_t a;
    asm("{ .reg .u64 t; cvta.to.shared.u64 t, %1; cvt.u32.u64 %0, t; }"
        : "=r"(a) : "l"(p));
    return a;
}

__device__ __forceinline__ uint32_t pack_bf2(float lo, float hi) {
    __nv_bfloat162 h = __floats2bfloat162_rn(lo, hi);
    return *(uint32_t*)&h;
}

#define CP_ASYNC16(saddr, gptr) \
    asm volatile("cp.async.cg.shared.global [%0], [%1], 16;" \
        :: "r"(saddr), "l"(gptr) : "memory")
#define CP_COMMIT() asm volatile("cp.async.commit_group;" ::: "memory")
#define CP_WAIT1()  asm volatile("cp.async.wait_group 1;" ::: "memory")
#define CP_WAIT0()  asm volatile("cp.async.wait_group 0;" ::: "memory")

#define LDMX4(r, addr) \
    asm volatile("ldmatrix.sync.aligned.m8n8.x4.shared.b16 {%0,%1,%2,%3}, [%4];" \
        : "=r"((r)[0]), "=r"((r)[1]), "=r"((r)[2]), "=r"((r)[3]) : "r"(addr))

// m16n8k16 bf16 MMA (sm_80 base ISA)
__device__ __forceinline__ void mma16n8k16(float d[4],
                                           const uint32_t a[4],
                                           const uint32_t b0, const uint32_t b1) {
    asm volatile(
        "mma.sync.aligned.m16n8k16.row.col.f32.bf16.bf16.f32 "
        "{%0,%1,%2,%3}, {%4,%5,%6,%7}, {%8,%9}, {%0,%1,%2,%3};"
        : "+f"(d[0]), "+f"(d[1]), "+f"(d[2]), "+f"(d[3])
        : "r"(a[0]), "r"(a[1]), "r"(a[2]), "r"(a[3]),
          "r"(b0), "r"(b1));
}

// ---------------------------------------------------------------------------
// Weight prep: fp32 wq/wk/wv/wp -> bf16 g_w ; pack bq||bk -> g_bqk
// ---------------------------------------------------------------------------
__global__ void __launch_bounds__(256)
prep_weights_kernel(const float* __restrict__ wq, const float* __restrict__ wk,
                    const float* __restrict__ wv, const float* __restrict__ wp,
                    const float* __restrict__ bq, const float* __restrict__ bk,
                    bf16* __restrict__ wout, float* __restrict__ bqk)
{
    const int i = blockIdx.x * 256 + threadIdx.x;  // float4 index, 65536 per matrix
    const float4* src[4] = { (const float4*)wq, (const float4*)wk,
                             (const float4*)wv, (const float4*)wp };
#pragma unroll
    for (int m = 0; m < 4; m++) {
        float4 v = src[m][i];
        uint2 o;
        o.x = pack_bf2(v.x, v.y);
        o.y = pack_bf2(v.z, v.w);
        ((uint2*)(wout + m * CC * CC))[i] = o;
    }
    if (blockIdx.x == 0) {
        const int t = threadIdx.x;   // 256 float4 = 1024 floats
        ((float4*)bqk)[t] = (t < 128) ? ((const float4*)bq)[t]
                                      : ((const float4*)bk)[t - 128];
    }
}

// ---------------------------------------------------------------------------
// GroupNorm + transpose: x [b][c][n] fp32 -> xn token-major [b][n][c] bf16
// Operates on a group of batches (pointers pre-offset).
// ---------------------------------------------------------------------------
__global__ void __launch_bounds__(256)
groupnorm_t_kernel(const float* __restrict__ x,
                   const float* __restrict__ gamma,
                   const float* __restrict__ beta,
                   bf16* __restrict__ xn)
{
    const int b = blockIdx.x / GG;
    const int g = blockIdx.x % GG;
    const size_t xbase = (size_t)b * CN + (size_t)g * CPG * NTOK;
    const int t = threadIdx.x;

    const float4* x4 = (const float4*)(x + xbase);
    const int M4 = (CPG * NTOK) / 4;   // 16384
    float s = 0.f, ss = 0.f;
    for (int i = t; i < M4; i += 256) {
        float4 v = x4[i];
        s  += v.x + v.y + v.z + v.w;
        ss += v.x*v.x + v.y*v.y + v.z*v.z + v.w*v.w;
    }
    __shared__ float rs[256], rq[256];
    rs[t] = s; rq[t] = ss;
    __syncthreads();
    for (int o = 128; o > 0; o >>= 1) {
        if (t < o) { rs[t] += rs[t+o]; rq[t] += rq[t+o]; }
        __syncthreads();
    }
    const float cnt  = (float)(CPG * NTOK);
    const float mean = rs[0] / cnt;
    const float var  = rq[0] / cnt - mean * mean;
    const float inv  = rsqrtf(var + EPSV);

    __shared__ float ts[64 * 65];
    const size_t obase = (size_t)b * CN + g * CPG;   // + n*CC + c
    for (int n0 = 0; n0 < NTOK; n0 += 64) {
        __syncthreads();
        for (int i = t; i < 64 * 16; i += 256) {
            const int c  = i >> 4;
            const int n4 = i & 15;
            const int cg = g * CPG + c;
            const float gm = gamma[cg] * inv;
            const float bt = beta[cg] - mean * gm;
            float4 v = *(const float4*)(x + (size_t)b * CN + (size_t)cg * NTOK + n0 + n4 * 4);
            ts[(n4*4 + 0) * 65 + c] = v.x * gm + bt;
            ts[(n4*4 + 1) * 65 + c] = v.y * gm + bt;
            ts[(n4*4 + 2) * 65 + c] = v.z * gm + bt;
            ts[(n4*4 + 3) * 65 + c] = v.w * gm + bt;
        }
        __syncthreads();
        for (int i = t; i < 64 * 16; i += 256) {
            const int n  = i >> 4;
            const int c4 = i & 15;
            uint2 o;
            o.x = pack_bf2(ts[n * 65 + c4*4 + 0], ts[n * 65 + c4*4 + 1]);
            o.y = pack_bf2(ts[n * 65 + c4*4 + 2], ts[n * 65 + c4*4 + 3]);
            *(uint2*)(xn + obase + (size_t)(n0 + n) * CC + c4 * 4) = o;
        }
    }
}

// ---------------------------------------------------------------------------
// Unified bf16 tensor-core GEMM, m16n8k16 + ldmatrix + fragment double-buffer.
// CTA tile 128x128, BK=64, 8 warps (4x2), warp tile 32x64, 3-stage cp.async.
// ---------------------------------------------------------------------------
#define BKT 64
#define LDT 72                         // bf16 elems per smem row (144 B)
#define STG_ELEM (2 * 128 * LDT)       // A+B per stage (bf16 elems)
#define STG_BYTE (STG_ELEM * 2)        // 36864 B

__global__ void __launch_bounds__(256, 2)
gemm_bf(const bf16* __restrict__ Ag, const bf16* __restrict__ Bg,
        void* __restrict__ Dg, int Ktot, int lda, int ldb, int ldc,
        long long sA, long long sB, long long sD,
        float alpha,
        const float* __restrict__ biasM, const float* __restrict__ biasN,
        const float* __restrict__ resid, int out_bf16)
{
    extern __shared__ bf16 sm[];

    const int tid  = threadIdx.x;
    const int lane = tid & 31;
    const int wid  = tid >> 5;
    const int wm   = (wid & 3) * 32;   // warp m offset in tile
    const int wn   = (wid >> 2) * 64;  // warp n offset in tile
    const int gtr  = lane >> 2;
    const int t4   = lane & 3;

    const int row16 = lane & 15;
    const int kh    = lane >> 4;       // 0 or 1

    const uint32_t smb = smem_u32(sm);
    const uint32_t aoff0 = (uint32_t)(((wm      + row16) * LDT + kh * 8) * 2);
    const uint32_t aoff1 = (uint32_t)(((wm + 16 + row16) * LDT + kh * 8) * 2);
    uint32_t boff[4];
#pragma unroll
    for (int p = 0; p < 4; ++p)
        boff[p] = (uint32_t)(((wn + p * 16 + row16) * LDT + kh * 8) * 2 + 128 * LDT * 2);

    const int bz = blockIdx.z;
    const bf16* A = Ag + (size_t)bz * sA;
    const bf16* B = Bg + (size_t)bz * sB;
    const int m0 = blockIdx.y * 128;
    const int n0 = blockIdx.x * 128;

    float acc[2][8][4];
#pragma unroll
    for (int i = 0; i < 2; i++)
#pragma unroll
        for (int j = 0; j < 8; j++)
#pragma unroll
            for (int q = 0; q < 4; q++) acc[i][j][q] = 0.f;

    const int NIT = Ktot / BKT;

    auto issue_loads = [&](int it, int stg) {
        const bf16* Asrc = A + (size_t)m0 * lda + it * BKT;
        const bf16* Bsrc = B + (size_t)n0 * ldb + it * BKT;
        const uint32_t aB = smb + stg * STG_BYTE;
        const uint32_t bB = aB + 128 * LDT * 2;
#pragma unroll
        for (int r = 0; r < 4; r++) {
            const int idx = tid + r * 256;     // 0..1023
            const int row = idx >> 3;          // 0..127
            const int q   = idx & 7;           // 16B chunk within 64-elem row
            CP_ASYNC16(aB + (uint32_t)(row * LDT + q * 8) * 2u,
                       Asrc + (size_t)row * lda + q * 8);
            CP_ASYNC16(bB + (uint32_t)(row * LDT + q * 8) * 2u,
                       Bsrc + (size_t)row * ldb + q * 8);
        }
        CP_COMMIT();
    };

    issue_loads(0, 0);
    if (NIT > 1) issue_loads(1, 1);

    uint32_t af[2][2][4];
    uint32_t bfr[2][8][2];

    for (int it = 0; it < NIT; ++it) {
        if (it + 1 < NIT) { CP_WAIT1(); } else { CP_WAIT0(); }
        __syncthreads();
        if (it + 2 < NIT) issue_loads(it + 2, (it + 2) % 3);

        const uint32_t sBase = smb + (it % 3) * STG_BYTE;

        {
            LDMX4(af[0][0], sBase + aoff0);
            LDMX4(af[0][1], sBase + aoff1);
#pragma unroll
            for (int p = 0; p < 4; ++p) {
                uint32_t rr[4];
                LDMX4(rr, sBase + boff[p]);
                bfr[0][2*p    ][0] = rr[0];
                bfr[0][2*p + 1][0] = rr[1];
                bfr[0][2*p    ][1] = rr[2];
                bfr[0][2*p + 1][1] = rr[3];
            }
        }

#pragma unroll
        for (int ks = 0; ks < 4; ++ks) {
            const int cur = ks & 1;
            const int nxt = cur ^ 1;
            if (ks < 3) {
                const uint32_t k1b = (uint32_t)((ks + 1) * 16 * 2);
                LDMX4(af[nxt][0], sBase + aoff0 + k1b);
                LDMX4(af[nxt][1], sBase + aoff1 + k1b);
#pragma unroll
                for (int p = 0; p < 4; ++p) {
                    uint32_t rr[4];
                    LDMX4(rr, sBase + boff[p] + k1b);
                    bfr[nxt][2*p    ][0] = rr[0];
                    bfr[nxt][2*p + 1][0] = rr[1];
                    bfr[nxt][2*p    ][1] = rr[2];
                    bfr[nxt][2*p + 1][1] = rr[3];
                }
            }
#pragma unroll
            for (int ma = 0; ma < 2; ++ma)
#pragma unroll
                for (int nb = 0; nb < 8; ++nb)
                    mma16n8k16(acc[ma][nb], af[cur][ma],
                               bfr[cur][nb][0], bfr[cur][nb][1]);
        }
    }

    // Epilogue
    const float* Rb = resid ? (resid + (size_t)bz * sD) : (const float*)0;
    float* Df = (float*)Dg + (size_t)bz * sD;
    bf16*  Dh = (bf16*)Dg + (size_t)bz * sD;
#pragma unroll
    for (int ma = 0; ma < 2; ++ma) {
        const int mrow0 = m0 + wm + ma * 16 + gtr;
        const int mrow1 = mrow0 + 8;
        const float bm0 = biasM ? biasM[mrow0] : 0.f;
        const float bm1 = biasM ? biasM[mrow1] : 0.f;
#pragma unroll
        for (int nb = 0; nb < 8; ++nb) {
            const int col = n0 + wn + nb * 8 + 2 * t4;
            float d0 = acc[ma][nb][0] * alpha + bm0;
            float d1 = acc[ma][nb][1] * alpha + bm0;
            float d2 = acc[ma][nb][2] * alpha + bm1;
            float d3 = acc[ma][nb][3] * alpha + bm1;
            if (biasN) {
                const float b0 = biasN[col], b1 = biasN[col + 1];
                d0 += b0; d1 += b1; d2 += b0; d3 += b1;
            }
            if (Rb) {
                const float2 r0 = *(const float2*)&Rb[(size_t)mrow0 * ldc + col];
                const float2 r1 = *(const float2*)&Rb[(size_t)mrow1 * ldc + col];
                d0 += r0.x; d1 += r0.y; d2 += r1.x; d3 += r1.y;
            }
            if (out_bf16) {
                *(uint32_t*)&Dh[(size_t)mrow0 * ldc + col] = pack_bf2(d0, d1);
                *(uint32_t*)&Dh[(size_t)mrow1 * ldc + col] = pack_bf2(d2, d3);
            } else {
                float2 o0 = { d0, d1 };
                float2 o1 = { d2, d3 };
                *(float2*)&Df[(size_t)mrow0 * ldc + col] = o0;
                *(float2*)&Df[(size_t)mrow1 * ldc + col] = o1;
            }
        }
    }
}

// ---------------------------------------------------------------------------
// Row softmax: one 256-thread block per row. fp32 S in, bf16 P out.
// ---------------------------------------------------------------------------
__global__ void __launch_bounds__(256)
softmax_rows(const float* __restrict__ S, bf16* __restrict__ P)
{
    const float4* R = (const float4*)(S + (size_t)blockIdx.x * NTOK);
    const int t = threadIdx.x;
    float4 v = R[t];

    float mx = fmaxf(fmaxf(v.x, v.y), fmaxf(v.z, v.w));
#pragma unroll
    for (int o = 16; o; o >>= 1) mx = fmaxf(mx, __shfl_xor_sync(0xffffffffu, mx, o));
    __shared__ float smax[8], ssum[8];
    if ((t & 31) == 0) smax[t >> 5] = mx;
    __syncthreads();
    float mm = smax[0];
#pragma unroll
    for (int i = 1; i < 8; ++i) mm = fmaxf(mm, smax[i]);

    float4 e;
    e.x = __expf(v.x - mm); e.y = __expf(v.y - mm);
    e.z = __expf(v.z - mm); e.w = __expf(v.w - mm);
    float su = e.x + e.y + e.z + e.w;
#pragma unroll
    for (int o = 16; o; o >>= 1) su += __shfl_xor_sync(0xffffffffu, su, o);
    if ((t & 31) == 0) ssum[t >> 5] = su;
    __syncthreads();
    float tot = 0.f;
#pragma unroll
    for (int i = 0; i < 8; ++i) tot += ssum[i];
    const float inv = 1.f / tot;

    uint2 o;
    o.x = pack_bf2(e.x * inv, e.y * inv);
    o.y = pack_bf2(e.z * inv, e.w * inv);
    *(uint2*)(P + (size_t)blockIdx.x * NTOK + t * 4) = o;
}

// ---------------------------------------------------------------------------
// Launcher — 4 batch groups pipelined across TWO streams (exactly ONE extra
// stream: the footprint validated by two passing runs). Groups 0,2 -> stream
// 0; groups 1,3 -> s2. Finer phases double the gap-fill opportunities.
// Stream/events created per call and leaked (host objects; graph replays).
// ---------------------------------------------------------------------------
extern "C" void kernel_launch(void* const* d_in, const int* in_sizes, int n_in,
                              void* d_out, int out_size)
{
    const float* x     = (const float*)d_in[0];
    const float* gamma = (const float*)d_in[1];
    const float* beta  = (const float*)d_in[2];
    const float* wq    = (const float*)d_in[3];
    const float* bq    = (const float*)d_in[4];
    const float* wk    = (const float*)d_in[5];
    const float* bk    = (const float*)d_in[6];
    const float* wv    = (const float*)d_in[7];
    const float* bv    = (const float*)d_in[8];
    const float* wp    = (const float*)d_in[9];
    const float* bp    = (const float*)d_in[10];
    float* out = (float*)d_out;

    bf16 *xn, *qk, *v, *p, *o, *w;
    float *s, *bqk;
    cudaGetSymbolAddress((void**)&xn,  g_xn);
    cudaGetSymbolAddress((void**)&qk,  g_qk);
    cudaGetSymbolAddress((void**)&v,   g_v);
    cudaGetSymbolAddress((void**)&s,   g_s);
    cudaGetSymbolAddress((void**)&p,   g_p);
    cudaGetSymbolAddress((void**)&o,   g_o);
    cudaGetSymbolAddress((void**)&w,   g_w);
    cudaGetSymbolAddress((void**)&bqk, g_bqk);
    const bf16* wqk = w;                    // wq||wk = 1024 x 512
    const bf16* wrv = w + 2 * CC * CC;
    const bf16* wrp = w + 3 * CC * CC;

    const int SMEM_DYN = 3 * STG_BYTE;      // 110592 B
    cudaFuncSetAttribute(gemm_bf, cudaFuncAttributeMaxDynamicSharedMemorySize, SMEM_DYN);

    const float scale = 0.044194173824159216f;  // 1/sqrt(512)

    // ONE side stream + fork/join events (footprint validated in R12/R14)
    cudaStream_t s2;
    cudaStreamCreateWithFlags(&s2, cudaStreamNonBlocking);
    cudaEvent_t evFork, evJoin;
    cudaEventCreateWithFlags(&evFork, cudaEventDisableTiming);
    cudaEventCreateWithFlags(&evJoin, cudaEventDisableTiming);

    // 0) weights -> bf16; pack bq||bk   (main stream), then fork
    prep_weights_kernel<<<256, 256>>>(wq, wk, wv, wp, bq, bk, w, bqk);
    cudaEventRecord(evFork, 0);
    cudaStreamWaitEvent(s2, evFork, 0);

    // 4 group chains, alternating streams (0,2 -> main; 1,3 -> s2)
    for (int g = 0; g < NGRP; ++g) {
        const int b0 = g * GB;
        const float* x_g   = x   + (size_t)b0 * CN;
        float*       out_g = out + (size_t)b0 * CN;
        bf16* xn_g = xn + (size_t)b0 * CN;
        bf16* qk_g = qk + (size_t)b0 * NTOK * 1024;
        bf16* v_g  = v  + (size_t)b0 * CN;
        float* s_g = s  + (size_t)b0 * SSTR;
        bf16* p_g  = p  + (size_t)b0 * SSTR;
        bf16* o_g  = o  + (size_t)b0 * CN;
        cudaStream_t sg = (g & 1) ? s2 : (cudaStream_t)0;

        // 1) GroupNorm -> token-major bf16 xn
        groupnorm_t_kernel<<<GB * GG, 256, 0, sg>>>(x_g, gamma, beta, xn_g);

        // 2) Packed QK: M=1024 N=1024 K=512
        gemm_bf<<<dim3(8, 8, GB), 256, SMEM_DYN, sg>>>(xn_g, wqk, qk_g,
            CC, CC, CC, 1024,
            (long long)CN, 0LL, (long long)(NTOK * 1024), 1.f, 0, bqk, 0, 1);

        // 3) V[c][j]: M=512 N=1024 K=512
        gemm_bf<<<dim3(8, 4, GB), 256, SMEM_DYN, sg>>>(wrv, xn_g, v_g,
            CC, CC, CC, NTOK,
            0LL, (long long)CN, (long long)CN, 1.f, bv, 0, 0, 1);

        // 4) S[i][j] = scale * q.k  M=N=1024 K=512 (fp32 out)
        gemm_bf<<<dim3(8, 8, GB), 256, SMEM_DYN, sg>>>(qk_g, qk_g + 512, s_g,
            CC, 1024, 1024, NTOK,
            (long long)(NTOK * 1024), (long long)(NTOK * 1024), (long long)SSTR,
            scale, 0, 0, 0, 0);

        // 5) row softmax fp32 -> bf16 P
        softmax_rows<<<GB * NTOK, 256, 0, sg>>>(s_g, p_g);

        // 6) O[i][c] = P.V  M=1024 N=512 K=1024
        gemm_bf<<<dim3(4, 8, GB), 256, SMEM_DYN, sg>>>(p_g, v_g, o_g,
            NTOK, NTOK, NTOK, CC,
            (long long)SSTR, (long long)CN, (long long)CN, 1.f, 0, 0, 0, 1);

        // 7) out = wp.O + bp + x  M=512 N=1024 K=512
        gemm_bf<<<dim3(8, 4, GB), 256, SMEM_DYN, sg>>>(wrp, o_g, out_g,
            CC, CC, CC, NTOK,
            0LL, (long long)CN, (long long)CN, 1.f, bp, 0, x_g, 0);
    }

    // join side stream back into the capture stream
    cudaEventRecord(evJoin, s2);
    cudaStreamWaitEvent(0, evJoin, 0);
}

// round 16
// speedup vs baseline: 1.3323x; 1.3323x over previous
#include <cuda_runtime.h>
#include <cuda_bf16.h>
#include <cstdint>
#include <math.h>

// ---------------------------------------------------------------------------
// Problem constants
// ---------------------------------------------------------------------------
#define BB   16
#define CC   512
#define NTOK 1024
#define GG   8
#define CPG  64
#define EPSV 1e-5f
#define CN   (CC * NTOK)     // 524288
#define SSTR (NTOK * NTOK)   // 1048576
#define NGRP 2               // batch groups (streams) — 1 extra stream only
#define GB   (BB / NGRP)     // 8 batches per group

typedef __nv_bfloat16 bf16;

// Scratch (device globals — no allocations allowed)
__device__ bf16  g_xn [BB * CN];          // token-major normalized input [b][n][c]
__device__ bf16  g_qk [BB * NTOK * 1024]; // packed [b][n][0:512)=Q, [512:1024)=K
__device__ bf16  g_v  [BB * CN];          // channel-major [b][c][j]
__device__ float g_s  [BB * SSTR];        // S[b][i][j] fp32 (pre-softmax)
__device__ bf16  g_p  [BB * SSTR];        // P[b][i][j] bf16 (post-softmax)
__device__ bf16  g_o  [BB * CN];          // [b][n][c]
__device__ bf16  g_w  [4 * CC * CC];      // bf16 wq, wk, wv, wp (wq||wk packed)
__device__ float g_bqk[1024];             // packed bq||bk

// ---------------------------------------------------------------------------
// Helpers
// ---------------------------------------------------------------------------
__device__ __forceinline__ uint32_t smem_u32(const void* p) {
    uint32_t a;
    asm("{ .reg .u64 t; cvta.to.shared.u64 t, %1; cvt.u32.u64 %0, t; }"
        : "=r"(a) : "l"(p));
    return a;
}

__device__ __forceinline__ uint32_t pack_bf2(float lo, float hi) {
    __nv_bfloat162 h = __floats2bfloat162_rn(lo, hi);
    return *(uint32_t*)&h;
}

#define CP_ASYNC16(saddr, gptr) \
    asm volatile("cp.async.cg.shared.global [%0], [%1], 16;" \
        :: "r"(saddr), "l"(gptr) : "memory")
#define CP_COMMIT() asm volatile("cp.async.commit_group;" ::: "memory")
#define CP_WAIT1()  asm volatile("cp.async.wait_group 1;" ::: "memory")
#define CP_WAIT0()  asm volatile("cp.async.wait_group 0;" ::: "memory")

#define LDMX4(r, addr) \
    asm volatile("ldmatrix.sync.aligned.m8n8.x4.shared.b16 {%0,%1,%2,%3}, [%4];" \
        : "=r"((r)[0]), "=r"((r)[1]), "=r"((r)[2]), "=r"((r)[3]) : "r"(addr))

// m16n8k16 bf16 MMA (sm_80 base ISA)
__device__ __forceinline__ void mma16n8k16(float d[4],
                                           const uint32_t a[4],
                                           const uint32_t b0, const uint32_t b1) {
    asm volatile(
        "mma.sync.aligned.m16n8k16.row.col.f32.bf16.bf16.f32 "
        "{%0,%1,%2,%3}, {%4,%5,%6,%7}, {%8,%9}, {%0,%1,%2,%3};"
        : "+f"(d[0]), "+f"(d[1]), "+f"(d[2]), "+f"(d[3])
        : "r"(a[0]), "r"(a[1]), "r"(a[2]), "r"(a[3]),
          "r"(b0), "r"(b1));
}

// ---------------------------------------------------------------------------
// Weight prep: fp32 wq/wk/wv/wp -> bf16 g_w ; pack bq||bk -> g_bqk
// ---------------------------------------------------------------------------
__global__ void __launch_bounds__(256)
prep_weights_kernel(const float* __restrict__ wq, const float* __restrict__ wk,
                    const float* __restrict__ wv, const float* __restrict__ wp,
                    const float* __restrict__ bq, const float* __restrict__ bk,
                    bf16* __restrict__ wout, float* __restrict__ bqk)
{
    const int i = blockIdx.x * 256 + threadIdx.x;  // float4 index, 65536 per matrix
    const float4* src[4] = { (const float4*)wq, (const float4*)wk,
                             (const float4*)wv, (const float4*)wp };
#pragma unroll
    for (int m = 0; m < 4; m++) {
        float4 v = src[m][i];
        uint2 o;
        o.x = pack_bf2(v.x, v.y);
        o.y = pack_bf2(v.z, v.w);
        ((uint2*)(wout + m * CC * CC))[i] = o;
    }
    if (blockIdx.x == 0) {
        const int t = threadIdx.x;   // 256 float4 = 1024 floats
        ((float4*)bqk)[t] = (t < 128) ? ((const float4*)bq)[t]
                                      : ((const float4*)bk)[t - 128];
    }
}

// ---------------------------------------------------------------------------
// GroupNorm + transpose: x [b][c][n] fp32 -> xn token-major [b][n][c] bf16
// Operates on a group of batches (pointers pre-offset).
// ---------------------------------------------------------------------------
__global__ void __launch_bounds__(256)
groupnorm_t_kernel(const float* __restrict__ x,
                   const float* __restrict__ gamma,
                   const float* __restrict__ beta,
                   bf16* __restrict__ xn)
{
    const int b = blockIdx.x / GG;
    const int g = blockIdx.x % GG;
    const size_t xbase = (size_t)b * CN + (size_t)g * CPG * NTOK;
    const int t = threadIdx.x;

    const float4* x4 = (const float4*)(x + xbase);
    const int M4 = (CPG * NTOK) / 4;   // 16384
    float s = 0.f, ss = 0.f;
    for (int i = t; i < M4; i += 256) {
        float4 v = x4[i];
        s  += v.x + v.y + v.z + v.w;
        ss += v.x*v.x + v.y*v.y + v.z*v.z + v.w*v.w;
    }
    __shared__ float rs[256], rq[256];
    rs[t] = s; rq[t] = ss;
    __syncthreads();
    for (int o = 128; o > 0; o >>= 1) {
        if (t < o) { rs[t] += rs[t+o]; rq[t] += rq[t+o]; }
        __syncthreads();
    }
    const float cnt  = (float)(CPG * NTOK);
    const float mean = rs[0] / cnt;
    const float var  = rq[0] / cnt - mean * mean;
    const float inv  = rsqrtf(var + EPSV);

    __shared__ float ts[64 * 65];
    const size_t obase = (size_t)b * CN + g * CPG;   // + n*CC + c
    for (int n0 = 0; n0 < NTOK; n0 += 64) {
        __syncthreads();
        for (int i = t; i < 64 * 16; i += 256) {
            const int c  = i >> 4;
            const int n4 = i & 15;
            const int cg = g * CPG + c;
            const float gm = gamma[cg] * inv;
            const float bt = beta[cg] - mean * gm;
            float4 v = *(const float4*)(x + (size_t)b * CN + (size_t)cg * NTOK + n0 + n4 * 4);
            ts[(n4*4 + 0) * 65 + c] = v.x * gm + bt;
            ts[(n4*4 + 1) * 65 + c] = v.y * gm + bt;
            ts[(n4*4 + 2) * 65 + c] = v.z * gm + bt;
            ts[(n4*4 + 3) * 65 + c] = v.w * gm + bt;
        }
        __syncthreads();
        for (int i = t; i < 64 * 16; i += 256) {
            const int n  = i >> 4;
            const int c4 = i & 15;
            uint2 o;
            o.x = pack_bf2(ts[n * 65 + c4*4 + 0], ts[n * 65 + c4*4 + 1]);
            o.y = pack_bf2(ts[n * 65 + c4*4 + 2], ts[n * 65 + c4*4 + 3]);
            *(uint2*)(xn + obase + (size_t)(n0 + n) * CC + c4 * 4) = o;
        }
    }
}

// ---------------------------------------------------------------------------
// Unified bf16 tensor-core GEMM, m16n8k16 + ldmatrix + fragment double-buffer.
// CTA tile 128x128, BK=64, 8 warps (4x2), warp tile 32x64, 3-stage cp.async.
// ---------------------------------------------------------------------------
#define BKT 64
#define LDT 72                         // bf16 elems per smem row (144 B)
#define STG_ELEM (2 * 128 * LDT)       // A+B per stage (bf16 elems)
#define STG_BYTE (STG_ELEM * 2)        // 36864 B

__global__ void __launch_bounds__(256, 2)
gemm_bf(const bf16* __restrict__ Ag, const bf16* __restrict__ Bg,
        void* __restrict__ Dg, int Ktot, int lda, int ldb, int ldc,
        long long sA, long long sB, long long sD,
        float alpha,
        const float* __restrict__ biasM, const float* __restrict__ biasN,
        const float* __restrict__ resid, int out_bf16)
{
    extern __shared__ bf16 sm[];

    const int tid  = threadIdx.x;
    const int lane = tid & 31;
    const int wid  = tid >> 5;
    const int wm   = (wid & 3) * 32;   // warp m offset in tile
    const int wn   = (wid >> 2) * 64;  // warp n offset in tile
    const int gtr  = lane >> 2;
    const int t4   = lane & 3;

    const int row16 = lane & 15;
    const int kh    = lane >> 4;       // 0 or 1

    const uint32_t smb = smem_u32(sm);
    const uint32_t aoff0 = (uint32_t)(((wm      + row16) * LDT + kh * 8) * 2);
    const uint32_t aoff1 = (uint32_t)(((wm + 16 + row16) * LDT + kh * 8) * 2);
    uint32_t boff[4];
#pragma unroll
    for (int p = 0; p < 4; ++p)
        boff[p] = (uint32_t)(((wn + p * 16 + row16) * LDT + kh * 8) * 2 + 128 * LDT * 2);

    const int bz = blockIdx.z;
    const bf16* A = Ag + (size_t)bz * sA;
    const bf16* B = Bg + (size_t)bz * sB;
    const int m0 = blockIdx.y * 128;
    const int n0 = blockIdx.x * 128;

    float acc[2][8][4];
#pragma unroll
    for (int i = 0; i < 2; i++)
#pragma unroll
        for (int j = 0; j < 8; j++)
#pragma unroll
            for (int q = 0; q < 4; q++) acc[i][j][q] = 0.f;

    const int NIT = Ktot / BKT;

    auto issue_loads = [&](int it, int stg) {
        const bf16* Asrc = A + (size_t)m0 * lda + it * BKT;
        const bf16* Bsrc = B + (size_t)n0 * ldb + it * BKT;
        const uint32_t aB = smb + stg * STG_BYTE;
        const uint32_t bB = aB + 128 * LDT * 2;
#pragma unroll
        for (int r = 0; r < 4; r++) {
            const int idx = tid + r * 256;     // 0..1023
            const int row = idx >> 3;          // 0..127
            const int q   = idx & 7;           // 16B chunk within 64-elem row
            CP_ASYNC16(aB + (uint32_t)(row * LDT + q * 8) * 2u,
                       Asrc + (size_t)row * lda + q * 8);
            CP_ASYNC16(bB + (uint32_t)(row * LDT + q * 8) * 2u,
                       Bsrc + (size_t)row * ldb + q * 8);
        }
        CP_COMMIT();
    };

    issue_loads(0, 0);
    if (NIT > 1) issue_loads(1, 1);

    uint32_t af[2][2][4];
    uint32_t bfr[2][8][2];

    for (int it = 0; it < NIT; ++it) {
        if (it + 1 < NIT) { CP_WAIT1(); } else { CP_WAIT0(); }
        __syncthreads();
        if (it + 2 < NIT) issue_loads(it + 2, (it + 2) % 3);

        const uint32_t sBase = smb + (it % 3) * STG_BYTE;

        {
            LDMX4(af[0][0], sBase + aoff0);
            LDMX4(af[0][1], sBase + aoff1);
#pragma unroll
            for (int p = 0; p < 4; ++p) {
                uint32_t rr[4];
                LDMX4(rr, sBase + boff[p]);
                bfr[0][2*p    ][0] = rr[0];
                bfr[0][2*p + 1][0] = rr[1];
                bfr[0][2*p    ][1] = rr[2];
                bfr[0][2*p + 1][1] = rr[3];
            }
        }

#pragma unroll
        for (int ks = 0; ks < 4; ++ks) {
            const int cur = ks & 1;
            const int nxt = cur ^ 1;
            if (ks < 3) {
                const uint32_t k1b = (uint32_t)((ks + 1) * 16 * 2);
                LDMX4(af[nxt][0], sBase + aoff0 + k1b);
                LDMX4(af[nxt][1], sBase + aoff1 + k1b);
#pragma unroll
                for (int p = 0; p < 4; ++p) {
                    uint32_t rr[4];
                    LDMX4(rr, sBase + boff[p] + k1b);
                    bfr[nxt][2*p    ][0] = rr[0];
                    bfr[nxt][2*p + 1][0] = rr[1];
                    bfr[nxt][2*p    ][1] = rr[2];
                    bfr[nxt][2*p + 1][1] = rr[3];
                }
            }
#pragma unroll
            for (int ma = 0; ma < 2; ++ma)
#pragma unroll
                for (int nb = 0; nb < 8; ++nb)
                    mma16n8k16(acc[ma][nb], af[cur][ma],
                               bfr[cur][nb][0], bfr[cur][nb][1]);
        }
    }

    // Epilogue
    const float* Rb = resid ? (resid + (size_t)bz * sD) : (const float*)0;
    float* Df = (float*)Dg + (size_t)bz * sD;
    bf16*  Dh = (bf16*)Dg + (size_t)bz * sD;
#pragma unroll
    for (int ma = 0; ma < 2; ++ma) {
        const int mrow0 = m0 + wm + ma * 16 + gtr;
        const int mrow1 = mrow0 + 8;
        const float bm0 = biasM ? biasM[mrow0] : 0.f;
        const float bm1 = biasM ? biasM[mrow1] : 0.f;
#pragma unroll
        for (int nb = 0; nb < 8; ++nb) {
            const int col = n0 + wn + nb * 8 + 2 * t4;
            float d0 = acc[ma][nb][0] * alpha + bm0;
            float d1 = acc[ma][nb][1] * alpha + bm0;
            float d2 = acc[ma][nb][2] * alpha + bm1;
            float d3 = acc[ma][nb][3] * alpha + bm1;
            if (biasN) {
                const float b0 = biasN[col], b1 = biasN[col + 1];
                d0 += b0; d1 += b1; d2 += b0; d3 += b1;
            }
            if (Rb) {
                const float2 r0 = *(const float2*)&Rb[(size_t)mrow0 * ldc + col];
                const float2 r1 = *(const float2*)&Rb[(size_t)mrow1 * ldc + col];
                d0 += r0.x; d1 += r0.y; d2 += r1.x; d3 += r1.y;
            }
            if (out_bf16) {
                *(uint32_t*)&Dh[(size_t)mrow0 * ldc + col] = pack_bf2(d0, d1);
                *(uint32_t*)&Dh[(size_t)mrow1 * ldc + col] = pack_bf2(d2, d3);
            } else {
                float2 o0 = { d0, d1 };
                float2 o1 = { d2, d3 };
                *(float2*)&Df[(size_t)mrow0 * ldc + col] = o0;
                *(float2*)&Df[(size_t)mrow1 * ldc + col] = o1;
            }
        }
    }
}

// ---------------------------------------------------------------------------
// Row softmax: one 256-thread block per row. fp32 S in, bf16 P out.
// ---------------------------------------------------------------------------
__global__ void __launch_bounds__(256)
softmax_rows(const float* __restrict__ S, bf16* __restrict__ P)
{
    const float4* R = (const float4*)(S + (size_t)blockIdx.x * NTOK);
    const int t = threadIdx.x;
    float4 v = R[t];

    float mx = fmaxf(fmaxf(v.x, v.y), fmaxf(v.z, v.w));
#pragma unroll
    for (int o = 16; o; o >>= 1) mx = fmaxf(mx, __shfl_xor_sync(0xffffffffu, mx, o));
    __shared__ float smax[8], ssum[8];
    if ((t & 31) == 0) smax[t >> 5] = mx;
    __syncthreads();
    float mm = smax[0];
#pragma unroll
    for (int i = 1; i < 8; ++i) mm = fmaxf(mm, smax[i]);

    float4 e;
    e.x = __expf(v.x - mm); e.y = __expf(v.y - mm);
    e.z = __expf(v.z - mm); e.w = __expf(v.w - mm);
    float su = e.x + e.y + e.z + e.w;
#pragma unroll
    for (int o = 16; o; o >>= 1) su += __shfl_xor_sync(0xffffffffu, su, o);
    if ((t & 31) == 0) ssum[t >> 5] = su;
    __syncthreads();
    float tot = 0.f;
#pragma unroll
    for (int i = 0; i < 8; ++i) tot += ssum[i];
    const float inv = 1.f / tot;

    uint2 o;
    o.x = pack_bf2(e.x * inv, e.y * inv);
    o.y = pack_bf2(e.z * inv, e.w * inv);
    *(uint2*)(P + (size_t)blockIdx.x * NTOK + t * 4) = o;
}

// ---------------------------------------------------------------------------
// Launcher — 2-way batch-group pipelining (the R14 config that measured
// 317.9us), with one refinement: group 1's GroupNorm depends only on x, so
// s2 starts it immediately; s2 waits for weight-prep only before its QK.
// Exactly ONE extra stream + two events (footprint validated three times).
// ---------------------------------------------------------------------------
extern "C" void kernel_launch(void* const* d_in, const int* in_sizes, int n_in,
                              void* d_out, int out_size)
{
    const float* x     = (const float*)d_in[0];
    const float* gamma = (const float*)d_in[1];
    const float* beta  = (const float*)d_in[2];
    const float* wq    = (const float*)d_in[3];
    const float* bq    = (const float*)d_in[4];
    const float* wk    = (const float*)d_in[5];
    const float* bk    = (const float*)d_in[6];
    const float* wv    = (const float*)d_in[7];
    const float* bv    = (const float*)d_in[8];
    const float* wp    = (const float*)d_in[9];
    const float* bp    = (const float*)d_in[10];
    float* out = (float*)d_out;

    bf16 *xn, *qk, *v, *p, *o, *w;
    float *s, *bqk;
    cudaGetSymbolAddress((void**)&xn,  g_xn);
    cudaGetSymbolAddress((void**)&qk,  g_qk);
    cudaGetSymbolAddress((void**)&v,   g_v);
    cudaGetSymbolAddress((void**)&s,   g_s);
    cudaGetSymbolAddress((void**)&p,   g_p);
    cudaGetSymbolAddress((void**)&o,   g_o);
    cudaGetSymbolAddress((void**)&w,   g_w);
    cudaGetSymbolAddress((void**)&bqk, g_bqk);
    const bf16* wqk = w;                    // wq||wk = 1024 x 512
    const bf16* wrv = w + 2 * CC * CC;
    const bf16* wrp = w + 3 * CC * CC;

    const int SMEM_DYN = 3 * STG_BYTE;      // 110592 B
    cudaFuncSetAttribute(gemm_bf, cudaFuncAttributeMaxDynamicSharedMemorySize, SMEM_DYN);

    const float scale = 0.044194173824159216f;  // 1/sqrt(512)

    // ONE side stream + fork/join events (validated footprint)
    cudaStream_t s2;
    cudaStreamCreateWithFlags(&s2, cudaStreamNonBlocking);
    cudaEvent_t evPrep, evJoin;
    cudaEventCreateWithFlags(&evPrep, cudaEventDisableTiming);
    cudaEventCreateWithFlags(&evJoin, cudaEventDisableTiming);

    // s2: GN(group 1) immediately — depends only on x
    {
        const int b1 = GB;
        groupnorm_t_kernel<<<GB * GG, 256, 0, s2>>>(
            x + (size_t)b1 * CN, gamma, beta, xn + (size_t)b1 * CN);
    }

    // main: weight prep, then GN(group 0)
    prep_weights_kernel<<<256, 256>>>(wq, wk, wv, wp, bq, bk, w, bqk);
    cudaEventRecord(evPrep, 0);
    groupnorm_t_kernel<<<GB * GG, 256>>>(x, gamma, beta, xn);

    // s2 needs weights before its first GEMM
    cudaStreamWaitEvent(s2, evPrep, 0);

    // per-group GEMM chains: group 0 on stream 0, group 1 on s2
    for (int g = 0; g < NGRP; ++g) {
        const int b0 = g * GB;
        const float* x_g   = x   + (size_t)b0 * CN;
        float*       out_g = out + (size_t)b0 * CN;
        bf16* xn_g = xn + (size_t)b0 * CN;
        bf16* qk_g = qk + (size_t)b0 * NTOK * 1024;
        bf16* v_g  = v  + (size_t)b0 * CN;
        float* s_g = s  + (size_t)b0 * SSTR;
        bf16* p_g  = p  + (size_t)b0 * SSTR;
        bf16* o_g  = o  + (size_t)b0 * CN;
        cudaStream_t sg = (g == 0) ? (cudaStream_t)0 : s2;

        // 2) Packed QK: M=1024 N=1024 K=512
        gemm_bf<<<dim3(8, 8, GB), 256, SMEM_DYN, sg>>>(xn_g, wqk, qk_g,
            CC, CC, CC, 1024,
            (long long)CN, 0LL, (long long)(NTOK * 1024), 1.f, 0, bqk, 0, 1);

        // 3) V[c][j]: M=512 N=1024 K=512
        gemm_bf<<<dim3(8, 4, GB), 256, SMEM_DYN, sg>>>(wrv, xn_g, v_g,
            CC, CC, CC, NTOK,
            0LL, (long long)CN, (long long)CN, 1.f, bv, 0, 0, 1);

        // 4) S[i][j] = scale * q.k  M=N=1024 K=512 (fp32 out)
        gemm_bf<<<dim3(8, 8, GB), 256, SMEM_DYN, sg>>>(qk_g, qk_g + 512, s_g,
            CC, 1024, 1024, NTOK,
            (long long)(NTOK * 1024), (long long)(NTOK * 1024), (long long)SSTR,
            scale, 0, 0, 0, 0);

        // 5) row softmax fp32 -> bf16 P
        softmax_rows<<<GB * NTOK, 256, 0, sg>>>(s_g, p_g);

        // 6) O[i][c] = P.V  M=1024 N=512 K=1024
        gemm_bf<<<dim3(4, 8, GB), 256, SMEM_DYN, sg>>>(p_g, v_g, o_g,
            NTOK, NTOK, NTOK, CC,
            (long long)SSTR, (long long)CN, (long long)CN, 1.f, 0, 0, 0, 1);

        // 7) out = wp.O + bp + x  M=512 N=1024 K=512
        gemm_bf<<<dim3(8, 4, GB), 256, SMEM_DYN, sg>>>(wrp, o_g, out_g,
            CC, CC, CC, NTOK,
            0LL, (long long)CN, (long long)CN, 1.f, bp, 0, x_g, 0);
    }

    // join side stream back into the capture stream
    cudaEventRecord(evJoin, s2);
    cudaStreamWaitEvent(0, evJoin, 0);
}